// round 12
// baseline (speedup 1.0000x reference)
#include <cuda_runtime.h>
#include <cuda_bf16.h>
#include <cstdint>
#include <cstddef>

// Problem constants (fixed by the reference).
#define NN   8192   // N_NODES
#define INF  256    // IN_FEATURES
#define OUTF 32     // OUT_FEATURES

// ---------------------------------------------------------------------------
// Scratch: HW = h @ W split into bf16 hi/lo, stored transposed [plane][n][k],
// with a k-permutation within each 16-block so a consuming lane's float4 of
// adj maps to a contiguous quad of packed B:
//   pos(k) = (k&2 ? 8 : 0) + ((k>>2)<<1) + (k&1)
// ---------------------------------------------------------------------------
__device__ __nv_bfloat16 g_B[2 * OUTF * NN];

// ---------------------------------------------------------------------------
// Kernel 1: HW = h @ W (fp32) -> hi/lo bf16 planes in g_B (permuted k).
// Also zero-inits out. Grid 256 x 256 thr; block = 32 rows; thread = 1 row x
// 4 output features. h staged coalesced in smem (pitch 257, conflict-free);
// W read via L1-broadcast LDG.128.
// ---------------------------------------------------------------------------
__global__ void __launch_bounds__(256) hw_kernel(const float* __restrict__ h,
                                                 const float* __restrict__ W,
                                                 float* __restrict__ out) {
    __shared__ float sh[32 * 257];
    const int t = threadIdx.x;

    // Zero-init out: 65536 threads x 1 float4 = 262144 floats exactly.
    reinterpret_cast<float4*>(out)[blockIdx.x * 256 + t] = make_float4(0.f, 0.f, 0.f, 0.f);

    const int rbase = blockIdx.x * 32;
    for (int i = t; i < 32 * 64; i += 256) {
        const int row = i >> 6, seg = i & 63;
        const float4 v = reinterpret_cast<const float4*>(h + (size_t)(rbase + row) * INF)[seg];
        float* d = &sh[row * 257 + seg * 4];
        d[0] = v.x; d[1] = v.y; d[2] = v.z; d[3] = v.w;
    }
    __syncthreads();

    const int row = t & 31;                 // lane -> row (conflict-free LDS)
    const int n0  = (t >> 5) * 4;           // warp -> 4 output features
    const float* hr = &sh[row * 257];
    float a0 = 0.f, a1 = 0.f, a2 = 0.f, a3 = 0.f;
#pragma unroll 8
    for (int k = 0; k < INF; ++k) {
        const float hv = hr[k];
        const float4 w4 = *reinterpret_cast<const float4*>(W + k * OUTF + n0);  // warp-broadcast
        a0 += hv * w4.x; a1 += hv * w4.y; a2 += hv * w4.z; a3 += hv * w4.w;
    }

    const int grow = rbase + row;
    const int ph   = grow & 15;
    const int p    = ((ph & 2) ? 8 : 0) | ((ph >> 2) << 1) | (ph & 1);
    const int kpos = (grow & ~15) | p;
    const float acc[4] = {a0, a1, a2, a3};
#pragma unroll
    for (int j = 0; j < 4; ++j) {
        const __nv_bfloat16 hi = __float2bfloat16_rn(acc[j]);
        const float rem        = acc[j] - __bfloat162float(hi);
        g_B[(size_t)(n0 + j) * NN + kpos]        = hi;                        // hi plane
        g_B[(size_t)(OUTF + n0 + j) * NN + kpos] = __float2bfloat16_rn(rem);  // lo plane
    }
}

// ---------------------------------------------------------------------------
// Kernel 2: out += adj @ HW via bf16 mma.sync (hi+lo planes).
//
// Grid = 2048: 128 m-tiles (BM=64) x 16 K-splits (512 K each).
// CTA = 128 thr = 4 warps; warp w = rows [w*16,(w+1)*16) x all n=32.
//
// A AND B both flow through a 3-stage cp.async ring (25600 B/stage):
//   A: 16 KB/stage; each 16B unit is placed at the address its consuming
//      lane reads with ld.shared.v4.f32 (layout [ks][row][quad]) — zero
//      padding, conflict-free, gmem side fully coalesced (warp = 512 B).
//   B: 9216 B/stage (pitch 144 -> conflict-free ldmatrix), as proven.
// 2 stages permanently in flight per CTA (~32 KB DRAM) -> DRAM saturation
// comes from async depth, not warp count. ONE __syncthreads per chunk.
// Epilogue: red.global.add.v2.f32 into zero-initialized out.
// ---------------------------------------------------------------------------
#define BK      64
#define BPITCH  144                    // bytes per B smem row (64 halfs + pad)
#define ASZ     16384                  // A bytes per stage
#define STAGE   (ASZ + 64 * BPITCH)    // 25600 B
#define SMEMT   (3 * STAGE)            // 76800 B dynamic smem
#define KSPLIT  16
#define KPER    (NN / KSPLIT)          // 512
#define CH      (KPER / BK)            // 8 chunks per CTA

#define MMA_BF16(ACC, A0, A1, A2, A3, B0, B1)                                   \
    asm volatile("mma.sync.aligned.m16n8k16.row.col.f32.bf16.bf16.f32 "         \
                 "{%0,%1,%2,%3}, {%4,%5,%6,%7}, {%8,%9}, {%0,%1,%2,%3};\n"      \
                 : "+f"((ACC)[0]), "+f"((ACC)[1]), "+f"((ACC)[2]), "+f"((ACC)[3])\
                 : "r"(A0), "r"(A1), "r"(A2), "r"(A3), "r"(B0), "r"(B1))

#define LDMX4(R0, R1, R2, R3, ADDR)                                             \
    asm volatile("ldmatrix.sync.aligned.m8n8.x4.shared.b16 {%0,%1,%2,%3}, [%4];\n"\
                 : "=r"(R0), "=r"(R1), "=r"(R2), "=r"(R3) : "r"(ADDR))

#define LDS128F(X0, X1, X2, X3, ADDR)                                           \
    asm volatile("ld.shared.v4.f32 {%0,%1,%2,%3}, [%4];\n"                      \
                 : "=f"(X0), "=f"(X1), "=f"(X2), "=f"(X3) : "r"(ADDR))

#define REDV2(PTR, X, Y)                                                        \
    asm volatile("red.global.add.v2.f32 [%0], {%1, %2};\n"                      \
                 :: "l"(PTR), "f"(X), "f"(Y) : "memory")

__global__ void __launch_bounds__(128) spmm_kernel(const float* __restrict__ adj,
                                                   float* __restrict__ out) {
    extern __shared__ __align__(16) char smem[];
    const uint32_t sb0 = static_cast<uint32_t>(__cvta_generic_to_shared(smem));

    const int t    = threadIdx.x;
    const int lane = t & 31;
    const int wm   = t >> 5;                    // 4 m-warps
    const int mt   = blockIdx.x & 127;          // m-tile (fast-varying: k-window L2 reuse)
    const int ksid = blockIdx.x >> 7;           // K-split id 0..15
    const int ctaM = mt * 64;
    const int kbase = ksid * KPER;

    // ---- Producer: A + B for one chunk into stage (chunk % 3), one group.
    auto cp_ab = [&](int chunk) {
        if (chunk < CH) {
            const uint32_t base = sb0 + (uint32_t)(chunk % 3) * STAGE;
            // A: 1024 x 16B units; unit u: row = u>>4, sub = u&15.
            // dst = [ks = sub>>2][row][quad = sub&3] -> consumer-native layout.
            const float* a0 = adj + (size_t)ctaM * NN + kbase + chunk * BK;
#pragma unroll
            for (int i = 0; i < 8; ++i) {
                const int u   = i * 128 + t;       // warp covers 512B contiguous
                const int row = u >> 4, sub = u & 15;
                const void* src = a0 + (size_t)row * NN + sub * 4;
                const uint32_t dst = base + ((sub >> 2) << 12) + row * 64 + ((sub & 3) << 4);
                asm volatile("cp.async.cg.shared.global [%0], [%1], 16;\n"
                             :: "r"(dst), "l"(src));
            }
            // B: 64 rows (plane*32+n) x 128B, pitch 144.
            const __nv_bfloat16* b0 = g_B + kbase + chunk * BK;
#pragma unroll
            for (int i = 0; i < 4; ++i) {
                const int idx = t + i * 128;
                const int row = idx >> 3, seg = idx & 7;
                const void* src = b0 + (size_t)row * NN + seg * 8;
                const uint32_t dst = base + ASZ + row * BPITCH + seg * 16;
                asm volatile("cp.async.cg.shared.global [%0], [%1], 16;\n"
                             :: "r"(dst), "l"(src));
            }
        }
        asm volatile("cp.async.commit_group;\n" ::);
    };

    // ---- Consumer lane offsets.
    const uint32_t aoff = (uint32_t)((wm * 16 + (lane >> 2)) * 64 + (lane & 3) * 16);
    const uint32_t brow = (uint32_t)(((lane >> 4) << 3) + (lane & 7));
    const uint32_t bko  = (uint32_t)(((lane >> 3) & 1) << 4);
    const uint32_t boff = brow * BPITCH + bko;

    float acc[4][4] = {};                       // 4 n8-tiles

    cp_ab(0); cp_ab(1);                         // prefetch depth 2

    for (int chunk = 0; chunk < CH; ++chunk) {
        asm volatile("cp.async.wait_group 1;\n" ::);   // group(chunk) complete
        __syncthreads();                               // stage(chunk-1) reusable
        cp_ab(chunk + 2);                              // refill into (chunk-1)'s stage

        const uint32_t sa  = sb0 + (uint32_t)(chunk % 3) * STAGE;
        const uint32_t sbB = sa + ASZ;
#pragma unroll
        for (int ks = 0; ks < 4; ++ks) {
            // A fragments: two conflict-free LDS.128 (rows r, r+8), cvt to bf16.
            float fx, fy, fz, fw, gx, gy, gz, gw;
            const uint32_t aa = sa + (ks << 12) + aoff;
            LDS128F(fx, fy, fz, fw, aa);
            LDS128F(gx, gy, gz, gw, aa + 512);
            __nv_bfloat162 b;
            uint32_t q0, q1, q2, q3;
            b = __floats2bfloat162_rn(fx, fy); q0 = *reinterpret_cast<uint32_t*>(&b);
            b = __floats2bfloat162_rn(gx, gy); q1 = *reinterpret_cast<uint32_t*>(&b);
            b = __floats2bfloat162_rn(fz, fw); q2 = *reinterpret_cast<uint32_t*>(&b);
            b = __floats2bfloat162_rn(gz, gw); q3 = *reinterpret_cast<uint32_t*>(&b);

            uint32_t h0,h1,h2,h3,h4,h5,h6,h7, l0,l1,l2,l3,l4,l5,l6,l7;
            const uint32_t ko = boff + ks * 32;
            LDMX4(h0,h1,h2,h3, sbB + ko);                    // hi, n0-15
            LDMX4(h4,h5,h6,h7, sbB + 16 * BPITCH + ko);      // hi, n16-31
            LDMX4(l0,l1,l2,l3, sbB + 32 * BPITCH + ko);      // lo, n0-15
            LDMX4(l4,l5,l6,l7, sbB + 48 * BPITCH + ko);      // lo, n16-31

            MMA_BF16(acc[0], q0,q1,q2,q3, h0,h1);
            MMA_BF16(acc[0], q0,q1,q2,q3, l0,l1);
            MMA_BF16(acc[1], q0,q1,q2,q3, h2,h3);
            MMA_BF16(acc[1], q0,q1,q2,q3, l2,l3);
            MMA_BF16(acc[2], q0,q1,q2,q3, h4,h5);
            MMA_BF16(acc[2], q0,q1,q2,q3, l4,l5);
            MMA_BF16(acc[3], q0,q1,q2,q3, h6,h7);
            MMA_BF16(acc[3], q0,q1,q2,q3, l6,l7);
        }
    }

    // ---- Epilogue: K-split partials via vector reductions (8B-aligned).
    const int row0 = ctaM + wm * 16 + (lane >> 2);
    const int col0 = (lane & 3) * 2;
#pragma unroll
    for (int tile = 0; tile < 4; ++tile) {
        float* o0 = out + (size_t)row0 * OUTF + tile * 8 + col0;
        REDV2(o0,            acc[tile][0], acc[tile][1]);
        REDV2(o0 + 8 * OUTF, acc[tile][2], acc[tile][3]);
    }
}

// ---------------------------------------------------------------------------
// Launch: h [8192*256] f32, adj [8192*8192] f32, W [256*32] f32; out f32.
// Plain launches (PDL regressed under graph capture). Dynamic smem 75 KB.
// ---------------------------------------------------------------------------
extern "C" void kernel_launch(void* const* d_in, const int* in_sizes, int n_in,
                              void* d_out, int out_size) {
    (void)in_sizes; (void)n_in; (void)out_size;
    const float* h   = reinterpret_cast<const float*>(d_in[0]);
    const float* adj = reinterpret_cast<const float*>(d_in[1]);
    const float* W   = reinterpret_cast<const float*>(d_in[2]);
    float* out       = reinterpret_cast<float*>(d_out);

    cudaFuncSetAttribute(spmm_kernel,
                         cudaFuncAttributeMaxDynamicSharedMemorySize, SMEMT);

    hw_kernel<<<NN / 32, 256>>>(h, W, out);                    // HW pack + out=0
    spmm_kernel<<<128 * KSPLIT, 128, SMEMT>>>(adj, out);       // 2048 CTAs
}

// round 13
// speedup vs baseline: 1.0987x; 1.0987x over previous
#include <cuda_runtime.h>
#include <cuda_fp16.h>
#include <cstdint>
#include <cstddef>

// Problem constants (fixed by the reference).
#define NN   8192   // N_NODES
#define INF  256    // IN_FEATURES
#define OUTF 32     // OUT_FEATURES

// ---------------------------------------------------------------------------
// Scratch: HW = h @ W in fp16, stored transposed [n][k] with a k-permutation
// within each 16-block so the A operand comes straight from gmem as one
// LDG.128 per lane per (kstep,row):
//   pos(k) = (k&2 ? 8 : 0) + ((k>>2)<<1) + (k&1)
// Single plane: adj in {0,1} is exact in fp16; HW in fp16 gives norm rel_err
// ~1.5e-4 against the fp32 reference (fixed seed) — well under the 1e-3 gate.
// ---------------------------------------------------------------------------
__device__ __half g_B[OUTF * NN];            // 512 KB

// ---------------------------------------------------------------------------
// Kernel 1: HW = h @ W (fp32) -> fp16 plane in g_B (permuted k).
// Also zero-inits out. Grid 256 x 256 thr; block = 32 rows; thread = 1 row x
// 4 output features. h staged coalesced in smem (pitch 257, conflict-free);
// W read via L1-broadcast LDG.128.
// ---------------------------------------------------------------------------
__global__ void __launch_bounds__(256) hw_kernel(const float* __restrict__ h,
                                                 const float* __restrict__ W,
                                                 float* __restrict__ out) {
    __shared__ float sh[32 * 257];
    const int t = threadIdx.x;

    // Zero-init out: 65536 threads x 1 float4 = 262144 floats exactly.
    reinterpret_cast<float4*>(out)[blockIdx.x * 256 + t] = make_float4(0.f, 0.f, 0.f, 0.f);

    const int rbase = blockIdx.x * 32;
    for (int i = t; i < 32 * 64; i += 256) {
        const int row = i >> 6, seg = i & 63;
        const float4 v = reinterpret_cast<const float4*>(h + (size_t)(rbase + row) * INF)[seg];
        float* d = &sh[row * 257 + seg * 4];
        d[0] = v.x; d[1] = v.y; d[2] = v.z; d[3] = v.w;
    }
    __syncthreads();

    const int row = t & 31;                 // lane -> row (conflict-free LDS)
    const int n0  = (t >> 5) * 4;           // warp -> 4 output features
    const float* hr = &sh[row * 257];
    float a0 = 0.f, a1 = 0.f, a2 = 0.f, a3 = 0.f;
#pragma unroll 8
    for (int k = 0; k < INF; ++k) {
        const float hv = hr[k];
        const float4 w4 = *reinterpret_cast<const float4*>(W + k * OUTF + n0);  // warp-broadcast
        a0 += hv * w4.x; a1 += hv * w4.y; a2 += hv * w4.z; a3 += hv * w4.w;
    }

    const int grow = rbase + row;
    const int ph   = grow & 15;
    const int p    = ((ph & 2) ? 8 : 0) | ((ph >> 2) << 1) | (ph & 1);
    const int kpos = (grow & ~15) | p;
    g_B[(size_t)(n0 + 0) * NN + kpos] = __float2half_rn(a0);
    g_B[(size_t)(n0 + 1) * NN + kpos] = __float2half_rn(a1);
    g_B[(size_t)(n0 + 2) * NN + kpos] = __float2half_rn(a2);
    g_B[(size_t)(n0 + 3) * NN + kpos] = __float2half_rn(a3);
}

// ---------------------------------------------------------------------------
// Kernel 2: out += adj_chunk @ HW via fp16 mma.sync (single plane).
// == R11's proven 51.7us skeleton with the lo plane removed: MMAs/chunk
//    32->16, ldmatrix 12->8, B smem+L2 traffic halved.
//
// Grid = 1024 CTAs: 128 m-tiles (BM=64) x 8 K-splits (1024 K each).
// CTA = 128 threads = 4 warps; warp w owns rows [w*16, w*16+16) x all n=32.
// A: direct gmem fragments (2 coalesced LDG.128 per lane per k16), whole-
//    chunk register prefetch, distance 1.
// B: 4-stage cp.async ring (18.4KB), prefetch depth 3, ONE syncthreads/chunk.
// Epilogue: red.global.add.v2.f32 into zero-initialized out.
// ---------------------------------------------------------------------------
#define BK      64
#define PITCH   144                    // bytes per B smem row (64 halfs + pad)
#define STAGEB  (32 * PITCH)           // 4608 B per stage (32 n-rows)
#define KSPLIT  8
#define KPER    (NN / KSPLIT)          // 1024
#define CH      (KPER / BK)            // 16 chunks per CTA

#define MMA_F16(ACC, A0, A1, A2, A3, B0, B1)                                    \
    asm volatile("mma.sync.aligned.m16n8k16.row.col.f32.f16.f16.f32 "           \
                 "{%0,%1,%2,%3}, {%4,%5,%6,%7}, {%8,%9}, {%0,%1,%2,%3};\n"      \
                 : "+f"((ACC)[0]), "+f"((ACC)[1]), "+f"((ACC)[2]), "+f"((ACC)[3])\
                 : "r"(A0), "r"(A1), "r"(A2), "r"(A3), "r"(B0), "r"(B1))

#define LDMX4(R0, R1, R2, R3, ADDR)                                             \
    asm volatile("ldmatrix.sync.aligned.m8n8.x4.shared.b16 {%0,%1,%2,%3}, [%4];\n"\
                 : "=r"(R0), "=r"(R1), "=r"(R2), "=r"(R3) : "r"(ADDR))

#define REDV2(PTR, X, Y)                                                        \
    asm volatile("red.global.add.v2.f32 [%0], {%1, %2};\n"                      \
                 :: "l"(PTR), "f"(X), "f"(Y) : "memory")

__global__ void __launch_bounds__(128) spmm_kernel(const float* __restrict__ adj,
                                                   float* __restrict__ out) {
    __shared__ __align__(16) char smem[4 * STAGEB];   // 18432 B
    const uint32_t sb0 = static_cast<uint32_t>(__cvta_generic_to_shared(smem));

    const int t    = threadIdx.x;
    const int lane = t & 31;
    const int wm   = t >> 5;                    // 4 m-warps
    const int mt   = blockIdx.x >> 3;           // m-tile 0..127
    const int ksid = blockIdx.x & 7;            // K-split id
    const int ctaM = mt * 64;
    const int kbase = ksid * KPER;

    // ---- A direct-fragment addressing: lane covers row r=lane/4 (and r+8),
    //      float4 at phys cols 4*(lane%4) within each k16 window.
    const int r  = lane >> 2;
    const int c4 = (lane & 3) << 2;
    const float* aptr = adj + (size_t)(ctaM + wm * 16 + r) * NN + kbase + c4;

    float4 pf[8];                               // prefetch: [kstep]{rows r, r+8}
    auto ld_a = [&](int chunk) {
        const float* p = aptr + chunk * BK;
#pragma unroll
        for (int ks = 0; ks < 4; ++ks) {
            pf[2 * ks]     = *reinterpret_cast<const float4*>(p + ks * 16);
            pf[2 * ks + 1] = *reinterpret_cast<const float4*>(p + ks * 16 + (size_t)8 * NN);
        }
    };

    // ---- B cp.async: 32 rows x 128B per chunk; 256 x 16B ops, 2/thread.
    auto cp_b = [&](int chunk) {
        if (chunk < CH) {
            const uint32_t bo = sb0 + (uint32_t)(chunk & 3) * STAGEB;
            const __half* s0 = g_B + kbase + chunk * BK;
#pragma unroll
            for (int i = 0; i < 2; ++i) {
                const int idx = t + i * 128;
                const int row = idx >> 3;       // 0..31 = n
                const int seg = idx & 7;
                const void* src = s0 + (size_t)row * NN + seg * 8;
                const uint32_t dst = bo + row * PITCH + seg * 16;
                asm volatile("cp.async.cg.shared.global [%0], [%1], 16;\n"
                             :: "r"(dst), "l"(src));
            }
        }
        asm volatile("cp.async.commit_group;\n" ::);
    };

    // ---- B ldmatrix lane offset within a 16-row group.
    const uint32_t brow = (uint32_t)(((lane >> 4) << 3) + (lane & 7));
    const uint32_t bko  = (uint32_t)(((lane >> 3) & 1) << 4);
    const uint32_t boff = brow * PITCH + bko;

    float acc[4][4] = {};                       // 4 n8-tiles
    uint32_t cur[16];                           // chunk's packed fp16 A frags

    ld_a(0);
    cp_b(0); cp_b(1); cp_b(2);                  // B prefetch depth 3

    for (int chunk = 0; chunk < CH; ++chunk) {
        // Convert prefetched A (frees pf for next chunk's loads).
#pragma unroll
        for (int ks = 0; ks < 4; ++ks) {
            const float4 f = pf[2 * ks], g = pf[2 * ks + 1];
            __half2 q0 = __floats2half2_rn(f.x, f.y);   // a0
            __half2 q1 = __floats2half2_rn(g.x, g.y);   // a1 (r+8)
            __half2 q2 = __floats2half2_rn(f.z, f.w);   // a2
            __half2 q3 = __floats2half2_rn(g.z, g.w);   // a3
            cur[4 * ks + 0] = *reinterpret_cast<uint32_t*>(&q0);
            cur[4 * ks + 1] = *reinterpret_cast<uint32_t*>(&q1);
            cur[4 * ks + 2] = *reinterpret_cast<uint32_t*>(&q2);
            cur[4 * ks + 3] = *reinterpret_cast<uint32_t*>(&q3);
        }
        if (chunk + 1 < CH) ld_a(chunk + 1);    // next chunk's A in flight

        asm volatile("cp.async.wait_group 2;\n" ::);   // B(chunk) arrived
        __syncthreads();                        // all warps done with chunk-1
        cp_b(chunk + 3);                        // overwrites chunk-1's stage: safe

        const uint32_t sb = sb0 + (uint32_t)(chunk & 3) * STAGEB;
#pragma unroll
        for (int ks = 0; ks < 4; ++ks) {
            uint32_t h0,h1,h2,h3,h4,h5,h6,h7;
            const uint32_t ko = boff + ks * 32;
            LDMX4(h0,h1,h2,h3, sb + ko);                    // n0-15
            LDMX4(h4,h5,h6,h7, sb + 16 * PITCH + ko);       // n16-31
            const uint32_t a0 = cur[4*ks], a1 = cur[4*ks+1],
                           a2 = cur[4*ks+2], a3 = cur[4*ks+3];
            MMA_F16(acc[0], a0,a1,a2,a3, h0,h1);
            MMA_F16(acc[1], a0,a1,a2,a3, h2,h3);
            MMA_F16(acc[2], a0,a1,a2,a3, h4,h5);
            MMA_F16(acc[3], a0,a1,a2,a3, h6,h7);
        }
    }

    // ---- Epilogue: K-split partials via vector reductions (8B-aligned).
    const int row0 = ctaM + wm * 16 + (lane >> 2);
    const int col0 = (lane & 3) * 2;
#pragma unroll
    for (int tile = 0; tile < 4; ++tile) {
        float* o0 = out + (size_t)row0 * OUTF + tile * 8 + col0;
        REDV2(o0,            acc[tile][0], acc[tile][1]);
        REDV2(o0 + 8 * OUTF, acc[tile][2], acc[tile][3]);
    }
}

// ---------------------------------------------------------------------------
// Launch: h [8192*256] f32, adj [8192*8192] f32, W [256*32] f32; out f32.
// Plain launches (PDL regressed under graph capture in R10).
// ---------------------------------------------------------------------------
extern "C" void kernel_launch(void* const* d_in, const int* in_sizes, int n_in,
                              void* d_out, int out_size) {
    (void)in_sizes; (void)n_in; (void)out_size;
    const float* h   = reinterpret_cast<const float*>(d_in[0]);
    const float* adj = reinterpret_cast<const float*>(d_in[1]);
    const float* W   = reinterpret_cast<const float*>(d_in[2]);
    float* out       = reinterpret_cast<float*>(d_out);

    hw_kernel<<<NN / 32, 256>>>(h, W, out);                 // HW pack + out=0
    spmm_kernel<<<(NN / 64) * KSPLIT, 128>>>(adj, out);     // 1024 CTAs
}